// round 17
// baseline (speedup 1.0000x reference)
#include <cuda_runtime.h>
#include <cuda_bf16.h>
#include <math.h>
#include <cstdint>

// ============================================================================
// BiDirectionalSymplecticLayer — fused persistent kernel, final-polish edition.
// 146 CTAs x 112 rows + 1 CTA x 32 rows (grid 147); 16 n-split warps, warp
// tile = all CTA rows x 16 cols. 3 barrier windows per pass (2 for MODE 4).
// bf16 state shadow lives in smem (T2 overlay, staged-A layout); fp32 master
// in global. bf16 m16n8k16, ldmatrix fragments, cross-pass weight prefetch.
// ============================================================================

#define D       256
#define FD      128
#define MTOT    16384
#define BHALF   8192
#define DT_MAG  0.1f
#define NTH     512

// smem layout (bytes)
#define OFF_H   0                        // T1: H, then G1 (MODE2 in-place)
#define OFF_G   57344                    // T2: G2  /  bf16 state (A-chunk layout)
#define OFF_B0  114688                   // B staging: 3 x (256 x 128B)
#define BBUF_SZ 32768
#define ACH_SZ  14336                    // one k64 A-chunk: 112 x 128B
#define SMEM_TOTAL (114688 + 3 * BBUF_SZ)   // 212992

__device__ float         g_S [MTOT * D];   // fp32 master state [q|p]
__device__ __nv_bfloat16 g_W1b [D * D];    // W1  [n][k]
__device__ __nv_bfloat16 g_W2b [D * D];    // W2  [n][k]
__device__ __nv_bfloat16 g_W1Tb[D * D];    // W1^T [n][k]
__device__ __nv_bfloat16 g_W2Tb[D * D];    // W2^T [n][k]

// ------------------------------- helpers ------------------------------------
__device__ __forceinline__ void cpa16(uint32_t dst, const void* src) {
    asm volatile("cp.async.cg.shared.global [%0], [%1], 16;"
                 :: "r"(dst), "l"(src) : "memory");
}
__device__ __forceinline__ uint32_t smem_u32(const void* p) {
    uint32_t r;
    asm("{ .reg .u64 t; cvta.to.shared.u64 t, %1; cvt.u32.u64 %0, t; }"
        : "=r"(r) : "l"(p));
    return r;
}
__device__ __forceinline__ void mma16(float* c, const uint32_t* a, const uint32_t* b) {
    asm volatile(
        "mma.sync.aligned.m16n8k16.row.col.f32.bf16.bf16.f32 "
        "{%0,%1,%2,%3}, {%4,%5,%6,%7}, {%8,%9}, {%0,%1,%2,%3};"
        : "+f"(c[0]), "+f"(c[1]), "+f"(c[2]), "+f"(c[3])
        : "r"(a[0]), "r"(a[1]), "r"(a[2]), "r"(a[3]), "r"(b[0]), "r"(b[1]));
}
#define LDMX4(r, addr) \
    asm volatile("ldmatrix.sync.aligned.m8n8.x4.shared.b16 {%0,%1,%2,%3}, [%4];" \
                 : "=r"((r)[0]), "=r"((r)[1]), "=r"((r)[2]), "=r"((r)[3]) \
                 : "r"(addr))
#define LDMX2(r, addr) \
    asm volatile("ldmatrix.sync.aligned.m8n8.x2.shared.b16 {%0,%1}, [%2];" \
                 : "=r"((r)[0]), "=r"((r)[1]) \
                 : "r"(addr))
__device__ __forceinline__ uint32_t pk2(float x, float y) {
    __nv_bfloat162 h = __floats2bfloat162_rn(x, y);
    return *reinterpret_cast<uint32_t*>(&h);
}
__device__ __forceinline__ float2 up2(uint32_t u) {
    __nv_bfloat162 h = *reinterpret_cast<__nv_bfloat162*>(&u);
    return make_float2(__bfloat162float(h.x), __bfloat162float(h.y));
}
__device__ __forceinline__ float ftanh(float x) {
    x = fminf(20.0f, fmaxf(-20.0f, x));
    float e;
    asm("ex2.approx.f32 %0, %1;" : "=f"(e) : "f"(x * 2.885390082f));
    float d = e + 1.0f;
    float y = __int_as_float(0x7EF311C3 - __float_as_int(d));
    y = y * (2.0f - d * y);
    y = y * (2.0f - d * y);
    return 1.0f - 2.0f * y;
}
// byte offset of state element (local row r, state col sc) in A-chunk layout
__device__ __forceinline__ uint32_t st_addr(int r, int sc) {
    int ch = sc >> 6, cl = sc & 63;
    return (uint32_t)(OFF_G + ch * ACH_SZ + r * 128 +
                      ((((cl >> 3) ^ (r & 7)) << 4) | ((cl << 1) & 15)));
}

// stage one k64 B chunk (rows x 128B) into a swizzled buffer; own group.
__device__ __forceinline__ void stageB_rows(uint32_t dst, const __nv_bfloat16* Bg0,
                                            int kc, int rows, int tid) {
    const __nv_bfloat16* Bg = Bg0 + kc * 64;
    const int n = rows >> 6;
    for (int i = 0; i < n; i++) {
        int idx = tid + (i << 9);
        int row = idx >> 3, c = idx & 7;
        cpa16(dst + row * 128 + ((c ^ (row & 7)) << 4),
              Bg + (size_t)row * D + c * 8);
    }
    asm volatile("cp.async.commit_group;" ::: "memory");
}

// --------------------------- prologue kernel --------------------------------
__global__ void prep_kernel(const float* __restrict__ W1,
                            const float* __restrict__ W2) {
    int idx = blockIdx.x * blockDim.x + threadIdx.x;
    int r = idx >> 8, c = idx & 255;
    __nv_bfloat16 v1 = __float2bfloat16(W1[idx]);
    __nv_bfloat16 v2 = __float2bfloat16(W2[idx]);
    g_W1b[idx] = v1;
    g_W2b[idx] = v2;
    g_W1Tb[c * D + r] = v1;
    g_W2Tb[c * D + r] = v2;
}

// ------------------------------ fused pass ----------------------------------
//  MODE 0: A = smem state,  B = g_W1Tb -> T1 = tanh(acc + b1)          [H]
//  MODE 1: A = T1,          B = g_W2Tb -> T2 = wout*(1-tanh(acc+b2)^2) [G2]
//  MODE 2: A = T2,          B = g_W2b  -> T1 = acc*(1 - T1^2) (in-place RAW)
//  MODE 3: A = T1,          B = g_W1b  -> full kick; state -> smem
//  MODE 4: A = T1,          B = g_W1b  -> half kick (p) + q refresh; 2 windows
template <int MODE, int NT, int F>
__device__ __forceinline__ void pass_gemm(char* smem, uint32_t sbase,
                                          int m0, int cbm, int bs,
                                          const __nv_bfloat16* nextB, int nextRows,
                                          const float* __restrict__ b1g,
                                          const float* __restrict__ b2g,
                                          const float* __restrict__ wog) {
    const int tid  = threadIdx.x;
    const int wid  = tid >> 5;
    const int lane = tid & 31;
    const int g    = lane >> 2;
    const int t    = lane & 3;
    const int wn   = wid * (NT * 8);

    const uint32_t* Ht  = (const uint32_t*)(smem + OFF_H);
    uint32_t*       Htw = (uint32_t*)(smem + OFF_H);
    uint32_t*       Gt  = (uint32_t*)(smem + OFF_G);

    const __nv_bfloat16* Bsrc =
        (MODE == 0) ? g_W1Tb : (MODE == 1) ? g_W2Tb :
        (MODE == 2) ? g_W2b : g_W1b;

    uint32_t BB[3];
#pragma unroll
    for (int i = 0; i < 3; i++) {
        int b = bs + i;  if (b >= 3) b -= 3;
        BB[i] = sbase + OFF_B0 + (uint32_t)b * BBUF_SZ;
    }

    // hoisted epilogue constants (columns known at entry; L1 latency hidden)
    float bv[NT][2], wv[NT][2];
    if (MODE == 0 || MODE == 1) {
        const float* bsr = (MODE == 0) ? b1g : b2g;
#pragma unroll
        for (int nf = 0; nf < NT; nf++) {
            int nc = wn + nf * 8 + 2 * t;
            bv[nf][0] = __ldg(bsr + nc);
            bv[nf][1] = __ldg(bsr + nc + 1);
            if (MODE == 1) {
                wv[nf][0] = __ldg(wog + nc);
                wv[nf][1] = __ldg(wog + nc + 1);
            }
        }
    }

    float acc[F][NT][4];
#pragma unroll
    for (int f = 0; f < F; f++)
#pragma unroll
        for (int nf = 0; nf < NT; nf++)
#pragma unroll
            for (int r = 0; r < 4; r++) acc[f][nf][r] = 0.0f;

    // per-lane fragment address pieces
    const int      x7    = lane & 7;
    const int      akh   = lane >> 4;
    const uint32_t aRowS = (uint32_t)(lane & 15) * 128;       // state-chunk A
    const uint32_t bRow  =
        (uint32_t)(wn + ((NT == 2) ? (((lane >> 4) << 3) + x7) : x7)) * 128;
    const int      bkh   = (lane >> 3) & 1;
    const int hi4w = akh << 2;
    const int row7 = x7 << 2;
    uint32_t rrb[F];
#pragma unroll
    for (int f = 0; f < F; f++)
        rrb[f] = sbase + ((MODE == 2) ? OFF_G : OFF_H) +
                 (uint32_t)(f * 16 + (lane & 15)) * 512;

    auto compute_chunk = [&](int kc, uint32_t bufB) {
        const uint32_t aB = sbase + OFF_G + (uint32_t)kc * ACH_SZ + aRowS;
        const uint32_t bB = bufB + bRow;
#pragma unroll
        for (int kk = 0; kk < 4; kk++) {
            const int kg = kc * 4 + kk;
            uint32_t a[F][4], bb[NT][2];
            if (MODE == 0) {
                const uint32_t sa = (uint32_t)((((kk << 1) + akh) ^ x7) << 4);
#pragma unroll
                for (int f = 0; f < F; f++) LDMX4(a[f], aB + f * 2048 + sa);
            } else {
                const uint32_t s4 = (uint32_t)((((kg << 3) + hi4w) ^ row7) << 2);
#pragma unroll
                for (int f = 0; f < F; f++) LDMX4(a[f], rrb[f] + s4);
            }
            if (NT == 2) {
                uint32_t r_[4];
                const uint32_t sb4 = (uint32_t)((((kk << 1) + bkh) ^ x7) << 4);
                LDMX4(r_, bB + sb4);
                bb[0][0] = r_[0];  bb[0][1] = r_[1];
                bb[NT-1][0] = r_[2];  bb[NT-1][1] = r_[3];
            } else {
                const uint32_t sb2 = (uint32_t)((((kk << 1) + bkh) ^ x7) << 4);
                LDMX2(bb[0], bB + sb2);
            }
#pragma unroll
            for (int f = 0; f < F; f++)
#pragma unroll
                for (int nf = 0; nf < NT; nf++)
                    mma16(acc[f][nf], a[f], bb[nf]);
        }
    };

    if (MODE != 4) {
        // window A: chunks 0+1 (prefetched); stage chunk 2
        asm volatile("cp.async.wait_group 0;" ::: "memory");
        __syncthreads();
        stageB_rows(BB[2], Bsrc, 2, NT * 128, tid);
        compute_chunk(0, BB[0]);
        compute_chunk(1, BB[1]);

        // window B: chunk 2; stage chunk 3 into buffer 0
        asm volatile("cp.async.wait_group 0;" ::: "memory");
        __syncthreads();
        stageB_rows(BB[0], Bsrc, 3, NT * 128, tid);
        compute_chunk(2, BB[2]);

        // window C: prefetch next pass's chunks 0,1 into bufs 1,2; compute 3
        asm volatile("cp.async.wait_group 0;" ::: "memory");
        __syncthreads();
        if (nextB) {
            stageB_rows(BB[1], nextB, 0, nextRows, tid);
            stageB_rows(BB[2], nextB, 1, nextRows, tid);
        }
        compute_chunk(3, BB[0]);
    } else {
        // MODE 4 (N=128 -> 16KB chunks): 2 windows.
        // window A: compute 0,1; stage chunks 2+3 into BB[2] lo/hi halves
        asm volatile("cp.async.wait_group 0;" ::: "memory");
        __syncthreads();
        stageB_rows(BB[2],         Bsrc, 2, 128, tid);
        stageB_rows(BB[2] + 16384, Bsrc, 3, 128, tid);
        compute_chunk(0, BB[0]);
        compute_chunk(1, BB[1]);

        // window B: prefetch next pass's chunks into BB[0], BB[1] (freed in
        // window A — run_evals does NOT advance bs after MODE 4, so the next
        // pass finds them in its BB[0], BB[1]); compute 2,3
        asm volatile("cp.async.wait_group 0;" ::: "memory");
        __syncthreads();
        if (nextB) {
            stageB_rows(BB[0], nextB, 0, nextRows, tid);
            stageB_rows(BB[1], nextB, 1, nextRows, tid);
        }
        compute_chunk(2, BB[2]);
        compute_chunk(3, BB[2] + 16384);
    }

    // ------------------------------ epilogue --------------------------------
#pragma unroll
    for (int f = 0; f < F; f++) {
        const int r = f * 16 + g;                // local row; r&7 == g
#pragma unroll
        for (int nf = 0; nf < NT; nf++) {
            const int nc = wn + nf * 8 + 2 * t;
            const int ws = (nc >> 1) ^ (g << 2);
            float c0 = acc[f][nf][0], c1 = acc[f][nf][1];
            float c2 = acc[f][nf][2], c3 = acc[f][nf][3];

            if (MODE == 0) {
                Htw[r * 128 + ws]       = pk2(ftanh(c0 + bv[nf][0]),
                                              ftanh(c1 + bv[nf][1]));
                Htw[(r + 8) * 128 + ws] = pk2(ftanh(c2 + bv[nf][0]),
                                              ftanh(c3 + bv[nf][1]));
            } else if (MODE == 1) {
                float t0 = ftanh(c0 + bv[nf][0]), t1 = ftanh(c1 + bv[nf][1]);
                float t2 = ftanh(c2 + bv[nf][0]), t3 = ftanh(c3 + bv[nf][1]);
                Gt[r * 128 + ws]       = pk2(wv[nf][0] * (1.0f - t0 * t0),
                                             wv[nf][1] * (1.0f - t1 * t1));
                Gt[(r + 8) * 128 + ws] = pk2(wv[nf][0] * (1.0f - t2 * t2),
                                             wv[nf][1] * (1.0f - t3 * t3));
            } else if (MODE == 2) {
                float2 h0 = up2(Ht[r * 128 + ws]);
                float2 h1 = up2(Ht[(r + 8) * 128 + ws]);
                Htw[r * 128 + ws]       = pk2(c0 * (1.0f - h0.x * h0.x),
                                              c1 * (1.0f - h0.y * h0.y));
                Htw[(r + 8) * 128 + ws] = pk2(c2 * (1.0f - h1.x * h1.x),
                                              c3 * (1.0f - h1.y * h1.y));
            } else {
                const int grow = m0 + r;
                const float dA = (grow < BHALF) ? DT_MAG : -DT_MAG;
                const float dB = (grow + 8 < BHALF) ? DT_MAG : -DT_MAG;
                if (NT == 1 || nc < FD) {        // p -= 0.5*dt*dH[:, :FD]
                    const int sc = FD + nc;
                    float2* S0 = (float2*)(g_S + (size_t)grow * D + sc);
                    float2* S1 = (float2*)(g_S + (size_t)(grow + 8) * D + sc);
                    float2 p0 = *S0, p1 = *S1;
                    p0.x -= 0.5f * dA * c0;  p0.y -= 0.5f * dA * c1;
                    p1.x -= 0.5f * dB * c2;  p1.y -= 0.5f * dB * c3;
                    *S0 = p0;  *S1 = p1;
                    *(uint32_t*)(smem + st_addr(r, sc))     = pk2(p0.x, p0.y);
                    *(uint32_t*)(smem + st_addr(r + 8, sc)) = pk2(p1.x, p1.y);
                } else {                          // q += dt*dH[:, FD:]
                    const int sc = nc - FD;
                    float2* S0 = (float2*)(g_S + (size_t)grow * D + sc);
                    float2* S1 = (float2*)(g_S + (size_t)(grow + 8) * D + sc);
                    float2 q0 = *S0, q1 = *S1;
                    q0.x += dA * c0;  q0.y += dA * c1;
                    q1.x += dB * c2;  q1.y += dB * c3;
                    *S0 = q0;  *S1 = q1;
                    *(uint32_t*)(smem + st_addr(r, sc))     = pk2(q0.x, q0.y);
                    *(uint32_t*)(smem + st_addr(r + 8, sc)) = pk2(q1.x, q1.y);
                }
            }
        }
    }

    // MODE 4 only kicked p; rebuild q chunks of the smem state from fp32
    // master. Skip on the final pass (nextB == nullptr).
    if (MODE == 4 && nextB) {
        for (int i = tid; i < cbm * 64; i += NTH) {
            int r = i >> 6, sc = (i & 63) * 2;
            float2 v = *(const float2*)(g_S + (size_t)(m0 + r) * D + sc);
            *(uint32_t*)(smem + st_addr(r, sc)) = pk2(v.x, v.y);
        }
    }
    // no trailing barrier: the next pass's window-A wait+sync orders all
    // epilogue smem writes before any read.
}

// run the 8 leapfrog iterations with compile-time F
template <int F>
__device__ __forceinline__ void run_evals(char* smem, uint32_t sbase,
                                          int m0, int cbm,
                                          const float* b1, const float* b2,
                                          const float* wo) {
    int bs = 0;
    auto inc = [&]() { bs = (bs == 2) ? 0 : bs + 1; };
#pragma unroll 1
    for (int it = 0; it < 8; it++) {
        pass_gemm<0, 2, F>(smem, sbase, m0, cbm, bs, g_W2Tb, 256, b1, b2, wo); inc();
        pass_gemm<1, 2, F>(smem, sbase, m0, cbm, bs, g_W2b, 256, b1, b2, wo);  inc();
        if ((it & 1) == 0) {
            pass_gemm<2, 2, F>(smem, sbase, m0, cbm, bs, g_W1b, 256, b1, b2, wo); inc();
            pass_gemm<3, 2, F>(smem, sbase, m0, cbm, bs, g_W1Tb, 256, b1, b2, wo); inc();
        } else {
            pass_gemm<2, 2, F>(smem, sbase, m0, cbm, bs, g_W1b, 128, b1, b2, wo); inc();
            if (it < 7) { pass_gemm<4, 1, F>(smem, sbase, m0, cbm, bs, g_W1Tb, 256, b1, b2, wo); }
            else        { pass_gemm<4, 1, F>(smem, sbase, m0, cbm, bs, nullptr, 0, b1, b2, wo); }
            // NOTE: no inc() after MODE 4 — its window-B prefetch lands in
            // BB[0], BB[1], which are the next pass's chunk-0/1 buffers.
        }
    }
}

// ------------------------------ fused kernel --------------------------------
__global__ void __launch_bounds__(NTH, 1)
fused_kernel(const float* __restrict__ b1, const float* __restrict__ b2,
             const float* __restrict__ wo, const float* __restrict__ x,
             float* __restrict__ out) {
    extern __shared__ __align__(1024) char smem[];
    const uint32_t sbase = smem_u32(smem);
    const int tid = threadIdx.x;
    const int cta = blockIdx.x;

    const int m0  = (cta < 146) ? cta * 112 : 16352;
    const int cbm = (cta < 146) ? 112 : 32;

    // prefetch first pass's B chunks (bufs 0,1) — overlaps init below
    stageB_rows(sbase + OFF_B0, g_W1Tb, 0, 256, tid);
    stageB_rows(sbase + OFF_B0 + BBUF_SZ, g_W1Tb, 1, 256, tid);

    // init this CTA's state: fp32 master in global, bf16 shadow in smem
    for (int i = tid; i < cbm * 128; i += NTH) {
        int r = i >> 7, f = i & 127;
        int grow = m0 + r;
        int xi = (grow < BHALF) ? grow : grow - BHALF;
        size_t xb = (size_t)xi * 8192;
        float xm  = x[xb + 4096 + f];
        float xm1 = x[xb + 3968 + f];
        float q = xm, p = xm - xm1;
        size_t srow = (size_t)grow * D;
        g_S[srow + f]      = q;
        g_S[srow + FD + f] = p;
        *(__nv_bfloat16*)(smem + st_addr(r, f))      = __float2bfloat16(q);
        *(__nv_bfloat16*)(smem + st_addr(r, FD + f)) = __float2bfloat16(p);
    }
    // (first pass's window-A barrier orders these smem writes)

    if (cbm == 112) run_evals<7>(smem, sbase, m0, cbm, b1, b2, wo);
    else            run_evals<2>(smem, sbase, m0, cbm, b1, b2, wo);

    // output: this CTA's rows -> disjoint column ranges of out
    __syncthreads();   // kick-epilogue g_S writes visible to all threads
    for (int i = tid; i < cbm * 64; i += NTH) {
        int r = i >> 6, c4 = i & 63;
        int grow = m0 + r;
        float4 v = *(const float4*)(g_S + (size_t)grow * D + c4 * 4);
        int bwd = grow >= BHALF;
        float* orow = out + (size_t)(bwd ? grow - BHALF : grow) * 768;
        if (bwd) *(float4*)(orow + c4 * 4) = v;          // [q_b | p_b]
        else     *(float4*)(orow + 512 + c4 * 4) = v;    // [q_f | p_f]
    }
    for (int i = tid; i < cbm * 128; i += NTH) {
        int r = i >> 7, f = i & 127;
        int grow = m0 + r;
        if (grow < BHALF) {                              // fwd rows write mid
            size_t xb = (size_t)grow * 8192;
            float xm  = x[xb + 4096 + f];
            float xm1 = x[xb + 3968 + f];
            float* orow = out + (size_t)grow * 768;
            orow[256 + f] = xm;          // q_mid
            orow[384 + f] = xm - xm1;    // p_mid
        }
    }
}

// ---------------------------------------------------------------------------
extern "C" void kernel_launch(void* const* d_in, const int* in_sizes, int n_in,
                              void* d_out, int out_size) {
    const float* x    = (const float*)d_in[0];
    const float* W1   = (const float*)d_in[1];
    const float* b1   = (const float*)d_in[2];
    const float* W2   = (const float*)d_in[3];
    const float* b2   = (const float*)d_in[4];
    const float* Wout = (const float*)d_in[5];
    float* out = (float*)d_out;

    cudaFuncSetAttribute(fused_kernel,
                         cudaFuncAttributeMaxDynamicSharedMemorySize, SMEM_TOTAL);

    prep_kernel<<<D * D / 256, 256>>>(W1, W2);
    fused_kernel<<<147, NTH, SMEM_TOTAL>>>(b1, b2, Wout, x, out);
}